// round 4
// baseline (speedup 1.0000x reference)
#include <cuda_runtime.h>
#include <cstdint>
#include <cstddef>

#define NMAX 50000
#define EMAX 1600000
#define NEG_BIG (-1.0e30f)

__device__ float g_Q[(size_t)NMAX * 128];    // Q scratch, reused as TMP
__device__ float g_qk[(size_t)NMAX * 512];   // [n][h*128+j]
__device__ float g_agg[(size_t)NMAX * 512];  // [n][h*128+j] normalized aggregate
__device__ int   g_rs[NMAX + 1];

// ---- packed f32x2 helpers (FFMA2: 2x fp32 FMA rate) ----
typedef unsigned long long ull;
__device__ __forceinline__ ull f2_pack(float x, float y) {
    ull r; asm("mov.b64 %0, {%1,%2};" : "=l"(r) : "f"(x), "f"(y)); return r;
}
__device__ __forceinline__ void f2_fma(ull& a, ull b, ull c) {
    asm("fma.rn.f32x2 %0, %1, %2, %0;" : "+l"(a) : "l"(b), "l"(c));
}
__device__ __forceinline__ float f2_sum(ull v) {
    float x, y; asm("mov.b64 {%0,%1}, %2;" : "=f"(x), "=f"(y) : "l"(v)); return x + y;
}

// ---- segment bounds from sorted center_id ----
__global__ void k_init_rs(int N, int E) {
    int t = blockIdx.x * blockDim.x + threadIdx.x;
    if (t <= N) g_rs[t] = E;
}
__global__ void k_bounds(const int* __restrict__ center, int E) {
    int e = blockIdx.x * blockDim.x + threadIdx.x;
    if (e >= E) return;
    int c = center[e];
    int p = (e == 0) ? -1 : center[e - 1];
    for (int n = p + 1; n <= c; n++) g_rs[n] = e;
}

// ---- Y[n,i] = sum_k X[n,k]*W[i*128+k] ----
__global__ __launch_bounds__(512) void k_dense128(const float* __restrict__ X,
                                                  const float* __restrict__ W,
                                                  float* __restrict__ Y, int N) {
    __shared__ float x_s[2][128];
    __shared__ float part_s[2][4][128];
    int t = threadIdx.x, i = t & 127, kq = t >> 7;
    ull w2[16];
    const float* wp = W + (size_t)i * 128 + kq * 32;
#pragma unroll
    for (int c = 0; c < 16; c++) { float2 v = *(const float2*)(wp + 2 * c); w2[c] = f2_pack(v.x, v.y); }
    for (int base = blockIdx.x * 2; base < N; base += gridDim.x * 2) {
        if (t < 64) {
            int r = t >> 5, c4 = t & 31, n = base + r;
            float4 v = (n < N) ? *(const float4*)(X + (size_t)n * 128 + c4 * 4)
                               : make_float4(0.f, 0.f, 0.f, 0.f);
            *(float4*)(&x_s[r][c4 * 4]) = v;
        }
        __syncthreads();
        ull a0 = 0ull, a1 = 0ull;
        const float* x0 = &x_s[0][kq * 32];
        const float* x1 = &x_s[1][kq * 32];
#pragma unroll
        for (int c = 0; c < 16; c++) {
            float2 u = *(const float2*)(x0 + 2 * c), v = *(const float2*)(x1 + 2 * c);
            f2_fma(a0, w2[c], f2_pack(u.x, u.y));
            f2_fma(a1, w2[c], f2_pack(v.x, v.y));
        }
        part_s[0][kq][i] = f2_sum(a0);
        part_s[1][kq][i] = f2_sum(a1);
        __syncthreads();
        if (t < 256) {
            int r = t >> 7, ii = t & 127, n = base + r;
            if (n < N)
                Y[(size_t)n * 128 + ii] = part_s[r][0][ii] + part_s[r][1][ii] +
                                          part_s[r][2][ii] + part_s[r][3][ii];
        }
        __syncthreads();
    }
}

// ---- qk[n,h*128+j] = SC * sum_d Q[n,h*32+d]*W_K[(h*32+d)*128+j] ----
__global__ __launch_bounds__(512) void k_qk(const float* __restrict__ Q,
                                            const float* __restrict__ WK, int N) {
    __shared__ float q_s[2][128];
    int t = threadIdx.x, h = t >> 7, j = t & 127;
    ull w2[16];
#pragma unroll
    for (int c = 0; c < 16; c++)
        w2[c] = f2_pack(WK[(size_t)(h * 32 + 2 * c) * 128 + j],
                        WK[(size_t)(h * 32 + 2 * c + 1) * 128 + j]);
    const float SC = 0.17677669529663687f;  // 1/sqrt(32)
    for (int base = blockIdx.x * 2; base < N; base += gridDim.x * 2) {
        if (t < 64) {
            int r = t >> 5, c4 = t & 31, n = base + r;
            float4 v = (n < N) ? *(const float4*)(Q + (size_t)n * 128 + c4 * 4)
                               : make_float4(0.f, 0.f, 0.f, 0.f);
            *(float4*)(&q_s[r][c4 * 4]) = v;
        }
        __syncthreads();
        ull a0 = 0ull, a1 = 0ull;
        const float* q0 = &q_s[0][h * 32];
        const float* q1 = &q_s[1][h * 32];
#pragma unroll
        for (int c = 0; c < 16; c++) {
            float2 u = *(const float2*)(q0 + 2 * c), v = *(const float2*)(q1 + 2 * c);
            f2_fma(a0, w2[c], f2_pack(u.x, u.y));
            f2_fma(a1, w2[c], f2_pack(v.x, v.y));
        }
        if (base < N)     g_qk[(size_t)base * 512 + t] = f2_sum(a0) * SC;
        if (base + 1 < N) g_qk[(size_t)(base + 1) * 512 + t] = f2_sum(a1) * SC;
        __syncthreads();
    }
}

// ---- TMP[n,i] = sum_j W_V[i*128+j] * AG[n,(i>>5)*128+j] ----
__global__ __launch_bounds__(512) void k_vagg(const float* __restrict__ WV,
                                              float* __restrict__ TMP, int N) {
    __shared__ float ag_s[2][512];
    __shared__ float part_s[2][4][128];
    int t = threadIdx.x, i = t & 127, kq = t >> 7, h = i >> 5;
    ull w2[16];
    const float* wp = WV + (size_t)i * 128 + kq * 32;
#pragma unroll
    for (int c = 0; c < 16; c++) { float2 v = *(const float2*)(wp + 2 * c); w2[c] = f2_pack(v.x, v.y); }
    for (int base = blockIdx.x * 2; base < N; base += gridDim.x * 2) {
        if (t < 256) {
            int r = t >> 7, c4 = t & 127, n = base + r;
            float4 v = (n < N) ? *(const float4*)(g_agg + (size_t)n * 512 + c4 * 4)
                               : make_float4(0.f, 0.f, 0.f, 0.f);
            *(float4*)(&ag_s[r][c4 * 4]) = v;
        }
        __syncthreads();
        ull a0 = 0ull, a1 = 0ull;
        const float* x0 = &ag_s[0][h * 128 + kq * 32];
        const float* x1 = &ag_s[1][h * 128 + kq * 32];
#pragma unroll
        for (int c = 0; c < 16; c++) {
            float2 u = *(const float2*)(x0 + 2 * c), v = *(const float2*)(x1 + 2 * c);
            f2_fma(a0, w2[c], f2_pack(u.x, u.y));
            f2_fma(a1, w2[c], f2_pack(v.x, v.y));
        }
        part_s[0][kq][i] = f2_sum(a0);
        part_s[1][kq][i] = f2_sum(a1);
        __syncthreads();
        if (t < 256) {
            int r = t >> 7, ii = t & 127, n = base + r;
            if (n < N)
                TMP[(size_t)n * 128 + ii] = part_s[r][0][ii] + part_s[r][1][ii] +
                                            part_s[r][2][ii] + part_s[r][3][ii];
        }
        __syncthreads();
    }
}

// ---- per-node single pass over h_E: online segment softmax + aggregation ----
#define CH 64
#define PADR 132
__global__ __launch_bounds__(256) void k_node(const float* __restrict__ hE, int N) {
    __shared__ float hE_s[CH * PADR];
    __shared__ float qk_s[4 * PADR];
    __shared__ float lgT[4 * 68];
    __shared__ float pT[4 * 68];
    __shared__ float m_s[4], s_s[4], sc_s[4];
    int t = threadIdx.x;
    int n = blockIdx.x;
    if (n >= N) return;
    int beg = g_rs[n], end = g_rs[n + 1];

    for (int idx = t; idx < 512; idx += 256) {
        int hh = idx >> 7, j = idx & 127;
        qk_s[hh * PADR + j] = g_qk[(size_t)n * 512 + idx];
    }
    if (t < 4) { m_s[t] = NEG_BIG; s_s[t] = 0.f; }
    int w = t >> 5, l = t & 31;
    int hh2 = w & 3, jh = w >> 2, j1 = jh * 64 + l;
    float accLo = 0.f, accHi = 0.f;
    __syncthreads();

    for (int cs = beg; cs < end; cs += CH) {
        int cnt = min(CH, end - cs);
        for (int idx = t; idx < cnt * 32; idx += 256) {
            int r = idx >> 5, c4 = idx & 31;
            float4 v = *(const float4*)(hE + (size_t)(cs + r) * 128 + c4 * 4);
            *(float4*)(&hE_s[r * PADR + c4 * 4]) = v;
        }
        __syncthreads();
        {   // logits: thread (e = t>>2, head = t&3)
            int e = t >> 2, hq = t & 3;
            float lg = NEG_BIG;
            if (e < cnt) {
                ull acc = 0ull;
                const float* qp = &qk_s[hq * PADR];
                const float* xp = &hE_s[e * PADR];
#pragma unroll
                for (int jj = 0; jj < 32; jj++) {
                    float4 q4 = *(const float4*)(qp + jj * 4);
                    float4 x4 = *(const float4*)(xp + jj * 4);
                    f2_fma(acc, f2_pack(q4.x, q4.y), f2_pack(x4.x, x4.y));
                    f2_fma(acc, f2_pack(q4.z, q4.w), f2_pack(x4.z, x4.w));
                }
                lg = f2_sum(acc);
            }
            lgT[hq * 68 + e] = lg;
        }
        __syncthreads();
        if (t < 128) {  // per-head running max + rescale factor
            int wh = t >> 5, l2 = t & 31;
            float v = fmaxf(lgT[wh * 68 + l2], lgT[wh * 68 + l2 + 32]);
#pragma unroll
            for (int o = 16; o; o >>= 1) v = fmaxf(v, __shfl_xor_sync(0xffffffffu, v, o));
            if (l2 == 0) {
                float old = m_s[wh], nm = fmaxf(old, v);
                sc_s[wh] = __expf(old - nm);
                m_s[wh] = nm;
            }
        }
        __syncthreads();
        {   // p = exp(l - m), zero-padded
            int e = t >> 2, hq = t & 3;
            pT[hq * 68 + e] = (e < cnt) ? __expf(lgT[hq * 68 + e] - m_s[hq]) : 0.f;
        }
        __syncthreads();
        if (t < 128) {  // running sum
            int wh = t >> 5, l2 = t & 31;
            float v = pT[wh * 68 + l2] + pT[wh * 68 + l2 + 32];
#pragma unroll
            for (int o = 16; o; o >>= 1) v += __shfl_xor_sync(0xffffffffu, v, o);
            if (l2 == 0) s_s[wh] = s_s[wh] * sc_s[wh] + v;
        }
        {   // accumulate: warp (head hh2, half jh); lane owns cols j1, j1+32
            float sc = sc_s[hh2];
            accLo *= sc; accHi *= sc;
            const float* pp = &pT[hh2 * 68];
#pragma unroll 4
            for (int e = 0; e < cnt; e++) {
                float p = pp[e];
                accLo = fmaf(p, hE_s[e * PADR + j1], accLo);
                accHi = fmaf(p, hE_s[e * PADR + j1 + 32], accHi);
            }
        }
        __syncthreads();
    }
    float inv = (end > beg) ? (1.0f / s_s[hh2]) : 0.f;
    g_agg[(size_t)n * 512 + hh2 * 128 + j1]      = accLo * inv;
    g_agg[(size_t)n * 512 + hh2 * 128 + j1 + 32] = accHi * inv;
}

extern "C" void kernel_launch(void* const* d_in, const int* in_sizes, int n_in,
                              void* d_out, int out_size) {
    const float* hV = (const float*)d_in[0];
    const float* hE = (const float*)d_in[1];
    const int* center = (const int*)d_in[2];
    const float* WQ = (const float*)d_in[5];
    const float* WK = (const float*)d_in[6];
    const float* WV = (const float*)d_in[7];
    const float* WO = (const float*)d_in[8];
    float* out = (float*)d_out;
    int N = in_sizes[0] / 128;
    int E = in_sizes[1] / 128;

    float *gQ;
    cudaGetSymbolAddress((void**)&gQ, g_Q);

    k_init_rs<<<(N + 256) / 256, 256>>>(N, E);
    k_bounds<<<(E + 255) / 256, 256>>>(center, E);
    k_dense128<<<592, 512>>>(hV, WQ, gQ, N);   // Q = h_V @ W_Q^T
    k_qk<<<592, 512>>>(gQ, WK, N);             // qk per node/head
    k_node<<<N, 256>>>(hE, N);                 // softmax + aggregate (single h_E pass)
    k_vagg<<<592, 512>>>(WV, gQ, N);           // TMP = W_V applied per head
    k_dense128<<<592, 512>>>(gQ, WO, out, N);  // out = TMP @ W_O^T
}

// round 5
// speedup vs baseline: 1.1745x; 1.1745x over previous
#include <cuda_runtime.h>
#include <cstdint>
#include <cstddef>

#define NMAX 50000
#define EMAX 1600000
#define NEG_BIG (-1.0e30f)

__device__ float g_Q[(size_t)NMAX * 128];    // Q scratch, reused as TMP
__device__ float g_qk[(size_t)NMAX * 512];   // [n][h*128+j]
__device__ float g_agg[(size_t)NMAX * 512];  // [n][h*128+j] normalized aggregate
__device__ int   g_rs[NMAX + 1];

// ---- packed f32x2 helpers (FFMA2: 2x fp32 FMA rate) ----
typedef unsigned long long ull;
__device__ __forceinline__ ull f2_pack(float x, float y) {
    ull r; asm("mov.b64 %0, {%1,%2};" : "=l"(r) : "f"(x), "f"(y)); return r;
}
__device__ __forceinline__ void f2_fma(ull& a, ull b, ull c) {
    asm("fma.rn.f32x2 %0, %1, %2, %0;" : "+l"(a) : "l"(b), "l"(c));
}
__device__ __forceinline__ float f2_sum(ull v) {
    float x, y; asm("mov.b64 {%0,%1}, %2;" : "=f"(x), "=f"(y) : "l"(v)); return x + y;
}

// ---- segment bounds from sorted center_id ----
__global__ void k_init_rs(int N, int E) {
    int t = blockIdx.x * blockDim.x + threadIdx.x;
    if (t <= N) g_rs[t] = E;
}
__global__ void k_bounds(const int* __restrict__ center, int E) {
    int e = blockIdx.x * blockDim.x + threadIdx.x;
    if (e >= E) return;
    int c = center[e];
    int p = (e == 0) ? -1 : center[e - 1];
    for (int n = p + 1; n <= c; n++) g_rs[n] = e;
}

#define RB 8  // rows per iteration in dense kernels

// ---- Y[n,i] = sum_k X[n,k]*W[i*128+k] ----
__global__ __launch_bounds__(512) void k_dense128(const float* __restrict__ X,
                                                  const float* __restrict__ W,
                                                  float* __restrict__ Y, int N) {
    __shared__ float x_s[RB][128];
    __shared__ float part_s[RB][4][128];
    int t = threadIdx.x, i = t & 127, kq = t >> 7;
    ull w2[16];
    const float* wp = W + (size_t)i * 128 + kq * 32;
#pragma unroll
    for (int c = 0; c < 16; c++) { float2 v = *(const float2*)(wp + 2 * c); w2[c] = f2_pack(v.x, v.y); }
    for (int base = blockIdx.x * RB; base < N; base += gridDim.x * RB) {
        if (t < RB * 32) {
            int r = t >> 5, c4 = t & 31, n = base + r;
            float4 v = (n < N) ? *(const float4*)(X + (size_t)n * 128 + c4 * 4)
                               : make_float4(0.f, 0.f, 0.f, 0.f);
            *(float4*)(&x_s[r][c4 * 4]) = v;
        }
        __syncthreads();
        ull a[RB];
#pragma unroll
        for (int r = 0; r < RB; r++) a[r] = 0ull;
#pragma unroll
        for (int c = 0; c < 16; c++) {
#pragma unroll
            for (int r = 0; r < RB; r++) {
                float2 u = *(const float2*)(&x_s[r][kq * 32 + 2 * c]);
                f2_fma(a[r], w2[c], f2_pack(u.x, u.y));
            }
        }
#pragma unroll
        for (int r = 0; r < RB; r++) part_s[r][kq][i] = f2_sum(a[r]);
        __syncthreads();
        for (int o = t; o < RB * 128; o += 512) {
            int r = o >> 7, ii = o & 127, n = base + r;
            if (n < N)
                Y[(size_t)n * 128 + ii] = part_s[r][0][ii] + part_s[r][1][ii] +
                                          part_s[r][2][ii] + part_s[r][3][ii];
        }
        __syncthreads();
    }
}

// ---- qk[n,h*128+j] = SC * sum_d Q[n,h*32+d]*W_K[(h*32+d)*128+j] ----
__global__ __launch_bounds__(512) void k_qk(const float* __restrict__ Q,
                                            const float* __restrict__ WK, int N) {
    __shared__ float q_s[RB][128];
    int t = threadIdx.x, h = t >> 7, j = t & 127;
    ull w2[16];
#pragma unroll
    for (int c = 0; c < 16; c++)
        w2[c] = f2_pack(WK[(size_t)(h * 32 + 2 * c) * 128 + j],
                        WK[(size_t)(h * 32 + 2 * c + 1) * 128 + j]);
    const float SC = 0.17677669529663687f;  // 1/sqrt(32)
    for (int base = blockIdx.x * RB; base < N; base += gridDim.x * RB) {
        if (t < RB * 32) {
            int r = t >> 5, c4 = t & 31, n = base + r;
            float4 v = (n < N) ? *(const float4*)(Q + (size_t)n * 128 + c4 * 4)
                               : make_float4(0.f, 0.f, 0.f, 0.f);
            *(float4*)(&q_s[r][c4 * 4]) = v;
        }
        __syncthreads();
        ull a[RB];
#pragma unroll
        for (int r = 0; r < RB; r++) a[r] = 0ull;
#pragma unroll
        for (int c = 0; c < 16; c++) {
#pragma unroll
            for (int r = 0; r < RB; r++) {
                float2 u = *(const float2*)(&q_s[r][h * 32 + 2 * c]);
                f2_fma(a[r], w2[c], f2_pack(u.x, u.y));
            }
        }
#pragma unroll
        for (int r = 0; r < RB; r++)
            if (base + r < N) g_qk[(size_t)(base + r) * 512 + t] = f2_sum(a[r]) * SC;
        __syncthreads();
    }
}

// ---- TMP[n,i] = sum_j W_V[i*128+j] * AG[n,(i>>5)*128+j] ----
__global__ __launch_bounds__(512) void k_vagg(const float* __restrict__ WV,
                                              float* __restrict__ TMP, int N) {
    __shared__ float ag_s[RB][512];
    __shared__ float part_s[RB][4][128];
    int t = threadIdx.x, i = t & 127, kq = t >> 7, h = i >> 5;
    ull w2[16];
    const float* wp = WV + (size_t)i * 128 + kq * 32;
#pragma unroll
    for (int c = 0; c < 16; c++) { float2 v = *(const float2*)(wp + 2 * c); w2[c] = f2_pack(v.x, v.y); }
    for (int base = blockIdx.x * RB; base < N; base += gridDim.x * RB) {
        for (int o = t; o < RB * 128; o += 512) {
            int r = o >> 7, c4 = o & 127, n = base + r;
            float4 v = (n < N) ? *(const float4*)(g_agg + (size_t)n * 512 + c4 * 4)
                               : make_float4(0.f, 0.f, 0.f, 0.f);
            *(float4*)(&ag_s[r][c4 * 4]) = v;
        }
        __syncthreads();
        ull a[RB];
#pragma unroll
        for (int r = 0; r < RB; r++) a[r] = 0ull;
#pragma unroll
        for (int c = 0; c < 16; c++) {
#pragma unroll
            for (int r = 0; r < RB; r++) {
                float2 u = *(const float2*)(&ag_s[r][h * 128 + kq * 32 + 2 * c]);
                f2_fma(a[r], w2[c], f2_pack(u.x, u.y));
            }
        }
#pragma unroll
        for (int r = 0; r < RB; r++) part_s[r][kq][i] = f2_sum(a[r]);
        __syncthreads();
        for (int o = t; o < RB * 128; o += 512) {
            int r = o >> 7, ii = o & 127, n = base + r;
            if (n < N)
                TMP[(size_t)n * 128 + ii] = part_s[r][0][ii] + part_s[r][1][ii] +
                                            part_s[r][2][ii] + part_s[r][3][ii];
        }
        __syncthreads();
    }
}

// ---- per-node single pass over h_E: online segment softmax + aggregation ----
#define CH 40
#define PADR 132
__global__ __launch_bounds__(256) void k_node(const float* __restrict__ hE, int N) {
    __shared__ float hE_s[CH * PADR];   // 21.1 KB
    __shared__ float qk_s[4 * PADR];    // 2.1 KB
    __shared__ float lgT[4 * 68];
    __shared__ float pT[4 * 68];
    __shared__ float m_s[4], s_s[4], sc_s[4];
    int t = threadIdx.x;
    int n = blockIdx.x;
    if (n >= N) return;
    int beg = g_rs[n], end = g_rs[n + 1];

    for (int idx = t; idx < 512; idx += 256) {
        int hh = idx >> 7, j = idx & 127;
        qk_s[hh * PADR + j] = g_qk[(size_t)n * 512 + idx];
    }
    if (t < 4) { m_s[t] = NEG_BIG; s_s[t] = 0.f; }
    int w = t >> 5, l = t & 31;
    int hh2 = w & 3, jh = w >> 2, j1 = jh * 64 + l;
    float accLo = 0.f, accHi = 0.f;
    __syncthreads();

    for (int cs = beg; cs < end; cs += CH) {
        int cnt = min(CH, end - cs);
        for (int idx = t; idx < cnt * 32; idx += 256) {
            int r = idx >> 5, c4 = idx & 31;
            float4 v = *(const float4*)(hE + (size_t)(cs + r) * 128 + c4 * 4);
            *(float4*)(&hE_s[r * PADR + c4 * 4]) = v;
        }
        __syncthreads();
        {   // logits: thread (e = t>>2, head = t&3)
            int e = t >> 2, hq = t & 3;
            float lg = NEG_BIG;
            if (e < cnt) {
                ull acc = 0ull;
                const float* qp = &qk_s[hq * PADR];
                const float* xp = &hE_s[e * PADR];
#pragma unroll
                for (int jj = 0; jj < 32; jj++) {
                    float4 q4 = *(const float4*)(qp + jj * 4);
                    float4 x4 = *(const float4*)(xp + jj * 4);
                    f2_fma(acc, f2_pack(q4.x, q4.y), f2_pack(x4.x, x4.y));
                    f2_fma(acc, f2_pack(q4.z, q4.w), f2_pack(x4.z, x4.w));
                }
                lg = f2_sum(acc);
            }
            lgT[hq * 68 + e] = lg;
        }
        __syncthreads();
        if (t < 128) {  // per-head running max + rescale factor
            int wh = t >> 5, l2 = t & 31;
            float v = fmaxf(lgT[wh * 68 + l2], lgT[wh * 68 + l2 + 32]);
#pragma unroll
            for (int o = 16; o; o >>= 1) v = fmaxf(v, __shfl_xor_sync(0xffffffffu, v, o));
            if (l2 == 0) {
                float old = m_s[wh], nm = fmaxf(old, v);
                sc_s[wh] = __expf(old - nm);
                m_s[wh] = nm;
            }
        }
        __syncthreads();
        {   // p = exp(l - m), zero-padded
            int e = t >> 2, hq = t & 3;
            pT[hq * 68 + e] = (e < cnt) ? __expf(lgT[hq * 68 + e] - m_s[hq]) : 0.f;
        }
        __syncthreads();
        if (t < 128) {  // running sum
            int wh = t >> 5, l2 = t & 31;
            float v = pT[wh * 68 + l2] + pT[wh * 68 + l2 + 32];
#pragma unroll
            for (int o = 16; o; o >>= 1) v += __shfl_xor_sync(0xffffffffu, v, o);
            if (l2 == 0) s_s[wh] = s_s[wh] * sc_s[wh] + v;
        }
        {   // accumulate: warp (head hh2, half jh); lane owns cols j1, j1+32
            float sc = sc_s[hh2];
            accLo *= sc; accHi *= sc;
            const float* pp = &pT[hh2 * 68];
#pragma unroll 4
            for (int e = 0; e < cnt; e++) {
                float p = pp[e];
                accLo = fmaf(p, hE_s[e * PADR + j1], accLo);
                accHi = fmaf(p, hE_s[e * PADR + j1 + 32], accHi);
            }
        }
        __syncthreads();
    }
    float inv = (end > beg) ? (1.0f / s_s[hh2]) : 0.f;
    g_agg[(size_t)n * 512 + hh2 * 128 + j1]      = accLo * inv;
    g_agg[(size_t)n * 512 + hh2 * 128 + j1 + 32] = accHi * inv;
}

extern "C" void kernel_launch(void* const* d_in, const int* in_sizes, int n_in,
                              void* d_out, int out_size) {
    const float* hV = (const float*)d_in[0];
    const float* hE = (const float*)d_in[1];
    const int* center = (const int*)d_in[2];
    const float* WQ = (const float*)d_in[5];
    const float* WK = (const float*)d_in[6];
    const float* WV = (const float*)d_in[7];
    const float* WO = (const float*)d_in[8];
    float* out = (float*)d_out;
    int N = in_sizes[0] / 128;
    int E = in_sizes[1] / 128;

    float *gQ;
    cudaGetSymbolAddress((void**)&gQ, g_Q);

    k_init_rs<<<(N + 256) / 256, 256>>>(N, E);
    k_bounds<<<(E + 255) / 256, 256>>>(center, E);
    k_dense128<<<592, 512>>>(hV, WQ, gQ, N);   // Q = h_V @ W_Q^T
    k_qk<<<592, 512>>>(gQ, WK, N);             // qk per node/head
    k_node<<<N, 256>>>(hE, N);                 // softmax + aggregate (single h_E pass)
    k_vagg<<<592, 512>>>(WV, gQ, N);           // TMP = W_V applied per head
    k_dense128<<<592, 512>>>(gQ, WO, out, N);  // out = TMP @ W_O^T
}